// round 3
// baseline (speedup 1.0000x reference)
#include <cuda_runtime.h>
#include <cuda_bf16.h>

#define DIM     1024
#define BATCH   16384
#define NLAYERS 18
#define BM 128
#define BN 128
#define BK 16
#define SST 24   // smem row stride in bf16 elements (conflict-free for frag loads)

// ---------------- static device scratch (no runtime allocation) ----------------
__device__ __align__(16) __nv_bfloat16 g_Wh[NLAYERS * DIM * DIM];
__device__ __align__(16) __nv_bfloat16 g_Wl[NLAYERS * DIM * DIM];
__device__ __align__(16) __nv_bfloat16 g_A0h[BATCH * DIM];
__device__ __align__(16) __nv_bfloat16 g_A0l[BATCH * DIM];
__device__ __align__(16) __nv_bfloat16 g_A1h[BATCH * DIM];
__device__ __align__(16) __nv_bfloat16 g_A1l[BATCH * DIM];
__device__ __align__(16) __nv_bfloat16 g_Rh [BATCH * DIM];
__device__ __align__(16) __nv_bfloat16 g_Rl [BATCH * DIM];

__device__ __forceinline__ void split1(float v, __nv_bfloat16& h, __nv_bfloat16& l) {
    h = __float2bfloat16(v);
    l = __float2bfloat16(v - __bfloat162float(h));
}

// ---------------- split input x into (hi, lo) bf16 pair + residual copy ----------------
__global__ void k_split(const float* __restrict__ x,
                        __nv_bfloat16* __restrict__ oh, __nv_bfloat16* __restrict__ ol,
                        __nv_bfloat16* __restrict__ rh, __nv_bfloat16* __restrict__ rl) {
    int i4 = blockIdx.x * blockDim.x + threadIdx.x;      // one float4 per thread
    float4 v = reinterpret_cast<const float4*>(x)[i4];
    __nv_bfloat16 h0,h1,h2,h3,l0,l1,l2,l3;
    split1(v.x,h0,l0); split1(v.y,h1,l1); split1(v.z,h2,l2); split1(v.w,h3,l3);
    __nv_bfloat162 H0; H0.x=h0; H0.y=h1;
    __nv_bfloat162 H1; H1.x=h2; H1.y=h3;
    __nv_bfloat162 L0; L0.x=l0; L0.y=l1;
    __nv_bfloat162 L1; L1.x=l2; L1.y=l3;
    __nv_bfloat162* OH = reinterpret_cast<__nv_bfloat162*>(oh);
    __nv_bfloat162* OL = reinterpret_cast<__nv_bfloat162*>(ol);
    __nv_bfloat162* RH = reinterpret_cast<__nv_bfloat162*>(rh);
    __nv_bfloat162* RL = reinterpret_cast<__nv_bfloat162*>(rl);
    int b = i4 * 2;
    OH[b] = H0; OH[b+1] = H1;
    OL[b] = L0; OL[b+1] = L1;
    RH[b] = H0; RH[b+1] = H1;
    RL[b] = L0; RL[b+1] = L1;
}

// ---------------- dequant + fold LoRA into dense weight, split to bf16 pair ----------------
// W[l][o][i] = (qw/15*2-1)*scale[l][o][i/16]  +  sum_r lb[l][o][r] * la[l][r][i]
__global__ void k_prep(const int* __restrict__ qw, const float* __restrict__ scale,
                       const float* __restrict__ la, const float* __restrict__ lb) {
    int idx = blockIdx.x * 256 + threadIdx.x;            // < 18*1024*1024
    int l   = idx >> 20;
    int rem = idx & 0xFFFFF;
    int o   = rem >> 10;
    int i   = rem & 1023;
    float q = (float)qw[idx];                            // qw flat == [l][o][i]
    float s = scale[(l << 16) + (o << 6) + (i >> 4)];
    float w = (q / 15.0f * 2.0f - 1.0f) * s;
    const float* lar = la + l * (32 * DIM) + i;          // la[l][r][i], stride DIM over r
    const float* lbr = lb + l * (DIM * 32) + o * 32;     // lb[l][o][r]
#pragma unroll
    for (int r = 0; r < 32; r++)
        w += lbr[r] * lar[r * DIM];
    __nv_bfloat16 wh, wl;
    split1(w, wh, wl);
    g_Wh[idx] = wh;
    g_Wl[idx] = wl;
}

// ---------------- fused GEMM layer ----------------
// C[M,N] = A[M,K] * W[N,K]^T  (3-term bf16 split: Ah*Wh + Ah*Wl + Al*Wh), fp32 accum.
// MODE 0: out = relu(C + bias), write bf16 pair
// MODE 1: out = C + bias + residual, write bf16 pair (LN follows)
// MODE 2: out = C + bias + residual, write fp32 to d_out
#define MMA_B16(d, a, b) \
  asm volatile( \
    "mma.sync.aligned.m16n8k16.row.col.f32.bf16.bf16.f32 " \
    "{%0,%1,%2,%3},{%4,%5,%6,%7},{%8,%9},{%0,%1,%2,%3};\n" \
    : "+f"(d[0]), "+f"(d[1]), "+f"(d[2]), "+f"(d[3]) \
    : "r"(a[0]), "r"(a[1]), "r"(a[2]), "r"(a[3]), "r"(b[0]), "r"(b[1]))

template<int MODE>
__global__ void __launch_bounds__(256)
k_gemm(const __nv_bfloat16* __restrict__ Ah, const __nv_bfloat16* __restrict__ Al,
       const __nv_bfloat16* __restrict__ Wh, const __nv_bfloat16* __restrict__ Wl,
       const float* __restrict__ bias,
       __nv_bfloat16* __restrict__ Oh, __nv_bfloat16* __restrict__ Ol,
       const __nv_bfloat16* __restrict__ Rh, const __nv_bfloat16* __restrict__ Rl,
       float* __restrict__ Of)
{
    __shared__ __nv_bfloat16 sAh[BM * SST], sAl[BM * SST];
    __shared__ __nv_bfloat16 sBh[BN * SST], sBl[BN * SST];

    const int tid = threadIdx.x;
    const int Mb = blockIdx.y * BM;
    const int Nb = blockIdx.x * BN;

    // ---- global -> smem staging (one uint4 = 8 bf16 per thread per tile) ----
    const int grow = tid >> 1;              // 0..127
    const int gcg  = (tid & 1) * 8;         // 0 or 8 (column group)
    const uint4* gAh = reinterpret_cast<const uint4*>(Ah + (size_t)(Mb + grow) * DIM + gcg);
    const uint4* gAl = reinterpret_cast<const uint4*>(Al + (size_t)(Mb + grow) * DIM + gcg);
    const uint4* gBh = reinterpret_cast<const uint4*>(Wh + (size_t)(Nb + grow) * DIM + gcg);
    const uint4* gBl = reinterpret_cast<const uint4*>(Wl + (size_t)(Nb + grow) * DIM + gcg);
    uint4* sAh4 = reinterpret_cast<uint4*>(sAh + grow * SST + gcg);
    uint4* sAl4 = reinterpret_cast<uint4*>(sAl + grow * SST + gcg);
    uint4* sBh4 = reinterpret_cast<uint4*>(sBh + grow * SST + gcg);
    uint4* sBl4 = reinterpret_cast<uint4*>(sBl + grow * SST + gcg);

    uint4 ra_h = gAh[0], ra_l = gAl[0], rb_h = gBh[0], rb_l = gBl[0];

    const int lane = tid & 31, wid = tid >> 5;
    const int wm = (wid & 1) * 64;          // warp M offset
    const int wn = (wid >> 1) * 32;         // warp N offset
    const int g  = lane >> 2;               // group id (0..7)
    const int tg = lane & 3;                // thread-in-group (0..3)

    const unsigned* A32h = reinterpret_cast<const unsigned*>(sAh);
    const unsigned* A32l = reinterpret_cast<const unsigned*>(sAl);
    const unsigned* B32h = reinterpret_cast<const unsigned*>(sBh);
    const unsigned* B32l = reinterpret_cast<const unsigned*>(sBl);

    float acc[4][4][4];
#pragma unroll
    for (int mi = 0; mi < 4; mi++)
#pragma unroll
        for (int ni = 0; ni < 4; ni++)
#pragma unroll
            for (int k = 0; k < 4; k++) acc[mi][ni][k] = 0.f;

#pragma unroll 1
    for (int ks = 0; ks < DIM / BK; ++ks) {
        *sAh4 = ra_h; *sAl4 = ra_l; *sBh4 = rb_h; *sBl4 = rb_l;
        __syncthreads();
        if (ks + 1 < DIM / BK) {            // prefetch next K-slab into regs
            int ko = (ks + 1) * 2;          // uint4 stride per BK=16 bf16
            ra_h = gAh[ko]; ra_l = gAl[ko]; rb_h = gBh[ko]; rb_l = gBl[ko];
        }

        // fragments (SST/2 = 12 words per smem row)
        unsigned fa[4][4], fb[4][2];
#pragma unroll
        for (int mi = 0; mi < 4; mi++) {
            int w0 = (wm + mi * 16 + g) * 12 + tg;
            fa[mi][0] = A32h[w0];       fa[mi][1] = A32h[w0 + 96];
            fa[mi][2] = A32h[w0 + 4];   fa[mi][3] = A32h[w0 + 100];
        }
#pragma unroll
        for (int ni = 0; ni < 4; ni++) {
            int w0 = (wn + ni * 8 + g) * 12 + tg;
            fb[ni][0] = B32h[w0];       fb[ni][1] = B32h[w0 + 4];
        }
        // term 1: Ah * Wh
#pragma unroll
        for (int mi = 0; mi < 4; mi++)
#pragma unroll
            for (int ni = 0; ni < 4; ni++) MMA_B16(acc[mi][ni], fa[mi], fb[ni]);
        // term 2: Ah * Wl
        {
            unsigned fbl[4][2];
#pragma unroll
            for (int ni = 0; ni < 4; ni++) {
                int w0 = (wn + ni * 8 + g) * 12 + tg;
                fbl[ni][0] = B32l[w0];  fbl[ni][1] = B32l[w0 + 4];
            }
#pragma unroll
            for (int mi = 0; mi < 4; mi++)
#pragma unroll
                for (int ni = 0; ni < 4; ni++) MMA_B16(acc[mi][ni], fa[mi], fbl[ni]);
        }
        // term 3: Al * Wh
        {
            unsigned fal[4][4];
#pragma unroll
            for (int mi = 0; mi < 4; mi++) {
                int w0 = (wm + mi * 16 + g) * 12 + tg;
                fal[mi][0] = A32l[w0];      fal[mi][1] = A32l[w0 + 96];
                fal[mi][2] = A32l[w0 + 4];  fal[mi][3] = A32l[w0 + 100];
            }
#pragma unroll
            for (int mi = 0; mi < 4; mi++)
#pragma unroll
                for (int ni = 0; ni < 4; ni++) MMA_B16(acc[mi][ni], fal[mi], fb[ni]);
        }
        __syncthreads();
    }

    // ---- epilogue ----
    auto emit = [&](int r, int c, float v0, float v1) {
        size_t off = (size_t)r * DIM + c;
        if (MODE >= 1) {
            __nv_bfloat162 rh2 = *reinterpret_cast<const __nv_bfloat162*>(Rh + off);
            __nv_bfloat162 rl2 = *reinterpret_cast<const __nv_bfloat162*>(Rl + off);
            v0 += __bfloat162float(rh2.x) + __bfloat162float(rl2.x);
            v1 += __bfloat162float(rh2.y) + __bfloat162float(rl2.y);
        }
        if (MODE == 0) { v0 = fmaxf(v0, 0.f); v1 = fmaxf(v1, 0.f); }
        if (MODE == 2) {
            *reinterpret_cast<float2*>(Of + off) = make_float2(v0, v1);
        } else {
            __nv_bfloat16 h0, l0, h1, l1;
            split1(v0, h0, l0); split1(v1, h1, l1);
            __nv_bfloat162 H; H.x = h0; H.y = h1;
            __nv_bfloat162 L; L.x = l0; L.y = l1;
            *reinterpret_cast<__nv_bfloat162*>(Oh + off) = H;
            *reinterpret_cast<__nv_bfloat162*>(Ol + off) = L;
        }
    };

#pragma unroll
    for (int mi = 0; mi < 4; mi++) {
#pragma unroll
        for (int ni = 0; ni < 4; ni++) {
            int r0 = Mb + wm + mi * 16 + g;
            int c0 = Nb + wn + ni * 8 + tg * 2;
            float b0 = bias[c0], b1 = bias[c0 + 1];
            emit(r0,     c0, acc[mi][ni][0] + b0, acc[mi][ni][1] + b1);
            emit(r0 + 8, c0, acc[mi][ni][2] + b0, acc[mi][ni][3] + b1);
        }
    }
}

// ---------------- LayerNorm over rows of 1024; writes next-layer pair + residual pair ----------------
__device__ __forceinline__ float blockSum256(float v, float* red) {
#pragma unroll
    for (int o = 16; o > 0; o >>= 1) v += __shfl_xor_sync(0xffffffffu, v, o);
    int w = threadIdx.x >> 5;
    if ((threadIdx.x & 31) == 0) red[w] = v;
    __syncthreads();
    float t = 0.f;
#pragma unroll
    for (int i = 0; i < 8; i++) t += red[i];
    __syncthreads();
    return t;
}

__global__ void k_ln(const __nv_bfloat16* __restrict__ Ih, const __nv_bfloat16* __restrict__ Il,
                     const float* __restrict__ gw, const float* __restrict__ gb,
                     __nv_bfloat16* __restrict__ Oh, __nv_bfloat16* __restrict__ Ol,
                     __nv_bfloat16* __restrict__ R2h, __nv_bfloat16* __restrict__ R2l)
{
    __shared__ float red[8];
    const int row = blockIdx.x;
    const int tid = threadIdx.x;
    const size_t base = (size_t)row * DIM;
    float x[4];
#pragma unroll
    for (int j = 0; j < 4; j++) {
        int c = tid + j * 256;
        x[j] = __bfloat162float(Ih[base + c]) + __bfloat162float(Il[base + c]);
    }
    float s = x[0] + x[1] + x[2] + x[3];
    float mu = blockSum256(s, red) * (1.0f / DIM);
    float d[4], s2 = 0.f;
#pragma unroll
    for (int j = 0; j < 4; j++) { d[j] = x[j] - mu; s2 += d[j] * d[j]; }
    float var = blockSum256(s2, red) * (1.0f / DIM);
    float inv = rsqrtf(var + 1e-5f);
#pragma unroll
    for (int j = 0; j < 4; j++) {
        int c = tid + j * 256;
        float y = d[j] * inv * gw[c] + gb[c];
        __nv_bfloat16 h, l;
        split1(y, h, l);
        Oh[base + c] = h;  Ol[base + c] = l;
        R2h[base + c] = h; R2l[base + c] = l;
    }
}

// ---------------- orchestration ----------------
extern "C" void kernel_launch(void* const* d_in, const int* in_sizes, int n_in,
                              void* d_out, int out_size) {
    (void)in_sizes; (void)n_in; (void)out_size;
    const float* x     = (const float*)d_in[0];
    const float* scale = (const float*)d_in[1];
    const float* bias  = (const float*)d_in[2];
    const float* la    = (const float*)d_in[3];
    const float* lb    = (const float*)d_in[4];
    const float* lnw   = (const float*)d_in[5];
    const float* lnb   = (const float*)d_in[6];
    const int*   qw    = (const int*)d_in[7];

    __nv_bfloat16 *Wh, *Wl, *A0h, *A0l, *A1h, *A1l, *Rh, *Rl;
    cudaGetSymbolAddress((void**)&Wh,  g_Wh);
    cudaGetSymbolAddress((void**)&Wl,  g_Wl);
    cudaGetSymbolAddress((void**)&A0h, g_A0h);
    cudaGetSymbolAddress((void**)&A0l, g_A0l);
    cudaGetSymbolAddress((void**)&A1h, g_A1h);
    cudaGetSymbolAddress((void**)&A1l, g_A1l);
    cudaGetSymbolAddress((void**)&Rh,  g_Rh);
    cudaGetSymbolAddress((void**)&Rl,  g_Rl);

    k_split<<<BATCH * DIM / 4 / 256, 256>>>(x, A0h, A0l, Rh, Rl);
    k_prep <<<NLAYERS * DIM * DIM / 256, 256>>>(qw, scale, la, lb);

    dim3 ggrid(DIM / BN, BATCH / BM);   // (8, 128)
    int li = 0;
    for (int blk = 0; blk < 6; ++blk) {
        const int W0 = li * DIM * DIM;
        k_gemm<0><<<ggrid, 256>>>(A0h, A0l, Wh + W0, Wl + W0, bias + li * DIM,
                                  A1h, A1l, nullptr, nullptr, nullptr);
        li++;
        const int W1 = li * DIM * DIM;
        k_gemm<0><<<ggrid, 256>>>(A1h, A1l, Wh + W1, Wl + W1, bias + li * DIM,
                                  A0h, A0l, nullptr, nullptr, nullptr);
        li++;
        const int W2 = li * DIM * DIM;
        if (blk < 5) {
            k_gemm<1><<<ggrid, 256>>>(A0h, A0l, Wh + W2, Wl + W2, bias + li * DIM,
                                      A1h, A1l, Rh, Rl, nullptr);
            li++;
            k_ln<<<BATCH, 256>>>(A1h, A1l, lnw + blk * DIM, lnb + blk * DIM,
                                 A0h, A0l, Rh, Rl);
        } else {
            k_gemm<2><<<ggrid, 256>>>(A0h, A0l, Wh + W2, Wl + W2, bias + li * DIM,
                                      nullptr, nullptr, Rh, Rl, (float*)d_out);
            li++;
        }
    }
}

// round 5
// speedup vs baseline: 1.0569x; 1.0569x over previous
#include <cuda_runtime.h>
#include <cuda_bf16.h>
#include <cstdint>

#define DIM     1024
#define BATCH   16384
#define NLAYERS 18

// ---------------- GEMM tiling ----------------
#define BM 128
#define BN 256
#define BK 64                     // bf16 per K-chunk = 128B rows
#define NCHUNK (DIM / BK)         // 16

// smem stage layout: Ah(16K) Al(16K) Wh(32K) Wl(32K) = 96KB, 2 stages = 192KB
#define OFF_AL 16384u
#define OFF_WH 32768u
#define OFF_WL 65536u
#define STAGE  98304u
#define SM_TOTAL (2 * 98304)

// ---------------- static device scratch ----------------
__device__ __align__(16) __nv_bfloat16 g_Wh[NLAYERS * DIM * DIM];
__device__ __align__(16) __nv_bfloat16 g_Wl[NLAYERS * DIM * DIM];
__device__ __align__(16) __nv_bfloat16 g_A0h[BATCH * DIM];
__device__ __align__(16) __nv_bfloat16 g_A0l[BATCH * DIM];
__device__ __align__(16) __nv_bfloat16 g_A1h[BATCH * DIM];
__device__ __align__(16) __nv_bfloat16 g_A1l[BATCH * DIM];
__device__ __align__(16) __nv_bfloat16 g_Rh [BATCH * DIM];
__device__ __align__(16) __nv_bfloat16 g_Rl [BATCH * DIM];

// ---------------- PTX helpers (compute_103-safe: cp.async / ldmatrix / mma only) ----
__device__ __forceinline__ uint32_t smem_u32(const void* p) {
    uint32_t a;
    asm("{ .reg .u64 t; cvta.to.shared.u64 t, %1; cvt.u32.u64 %0, t; }" : "=r"(a) : "l"(p));
    return a;
}
#define CP_ASYNC16(dst, src) \
    asm volatile("cp.async.cg.shared.global [%0], [%1], 16;\n" :: "r"(dst), "l"(src))
#define CP_COMMIT() asm volatile("cp.async.commit_group;\n" ::: "memory")
#define CP_WAIT1()  asm volatile("cp.async.wait_group 1;\n" ::: "memory")
#define CP_WAIT0()  asm volatile("cp.async.wait_group 0;\n" ::: "memory")

#define LDSM_X4(r0, r1, r2, r3, addr) \
    asm volatile("ldmatrix.sync.aligned.m8n8.x4.shared.b16 {%0,%1,%2,%3}, [%4];\n" \
                 : "=r"(r0), "=r"(r1), "=r"(r2), "=r"(r3) : "r"(addr))

#define MMA4(d, a0, a1, a2, a3, b0, b1) \
    asm volatile("mma.sync.aligned.m16n8k16.row.col.f32.bf16.bf16.f32 " \
                 "{%0,%1,%2,%3},{%4,%5,%6,%7},{%8,%9},{%0,%1,%2,%3};\n" \
                 : "+f"((d)[0]), "+f"((d)[1]), "+f"((d)[2]), "+f"((d)[3]) \
                 : "r"(a0), "r"(a1), "r"(a2), "r"(a3), "r"(b0), "r"(b1))

__device__ __forceinline__ void split1(float v, __nv_bfloat16& h, __nv_bfloat16& l) {
    h = __float2bfloat16(v);
    l = __float2bfloat16(v - __bfloat162float(h));
}

// stage loader: 24 cp.async x16B per thread; SW128 swizzle on 128B rows
__device__ __forceinline__ void load_chunk(
    uint32_t st, int c, int tid,
    const char* pAh, const char* pAl, const char* pWh, const char* pWl)
{
    const uint32_t koff = (uint32_t)c * 128u;
#pragma unroll
    for (int i = 0; i < 8; i++) {                 // A: Ah then Al, 128 rows each
        int idx = tid + i * 256;
        int tsr = idx >> 10;
        int r   = (idx >> 3) & 127;
        int g   = idx & 7;
        const char* src = (tsr ? pAl : pAh) + (size_t)r * 2048 + koff + (size_t)(g * 16);
        uint32_t dst = st + (uint32_t)tsr * OFF_AL + (uint32_t)(r * 128)
                     + (uint32_t)(((unsigned)(g * 16)) ^ (((unsigned)r & 7u) << 4));
        CP_ASYNC16(dst, src);
    }
#pragma unroll
    for (int i = 0; i < 16; i++) {                // W: Wh then Wl, 256 rows each
        int idx = tid + i * 256;
        int tsr = idx >> 11;
        int r   = (idx >> 3) & 255;
        int g   = idx & 7;
        const char* src = (tsr ? pWl : pWh) + (size_t)r * 2048 + koff + (size_t)(g * 16);
        uint32_t dst = st + OFF_WH + (uint32_t)tsr * 32768u + (uint32_t)(r * 128)
                     + (uint32_t)(((unsigned)(g * 16)) ^ (((unsigned)r & 7u) << 4));
        CP_ASYNC16(dst, src);
    }
    CP_COMMIT();
}

// ---------------- fused GEMM layer ----------------
// C[BM,BN] = A[BM,K] * W[BN,K]^T, 3-term bf16 split (Ah*Wh + Al*Wh + Ah*Wl), fp32 accum.
// MODE 0: relu(C+bias) -> bf16 pair | MODE 1: C+bias+res -> bf16 pair | MODE 2: C+bias+res -> fp32
template<int MODE>
__global__ void __launch_bounds__(256, 1)
k_gemm(const __nv_bfloat16* __restrict__ Ah, const __nv_bfloat16* __restrict__ Al,
       const __nv_bfloat16* __restrict__ Wh, const __nv_bfloat16* __restrict__ Wl,
       const float* __restrict__ bias,
       __nv_bfloat16* __restrict__ Oh, __nv_bfloat16* __restrict__ Ol,
       const __nv_bfloat16* __restrict__ Rh, const __nv_bfloat16* __restrict__ Rl,
       float* __restrict__ Of)
{
    extern __shared__ char smem[];
    const uint32_t sb = smem_u32(smem);
    const int tid = threadIdx.x, wid = tid >> 5, lane = tid & 31;
    const int Mb = blockIdx.y * BM, Nb = blockIdx.x * BN;
    const int wm = (wid & 1) * 64, wn = (wid >> 1) * 64;

    const char* pAh = (const char*)(Ah + (size_t)Mb * DIM);
    const char* pAl = (const char*)(Al + (size_t)Mb * DIM);
    const char* pWh = (const char*)(Wh + (size_t)Nb * DIM);
    const char* pWl = (const char*)(Wl + (size_t)Nb * DIM);

    // ldmatrix lane addressing constants
    const int l7  = lane & 7;
    const int l15 = lane & 15;
    const int lhi = lane >> 4;                  // 0/1 -> k-half chunk
    const int lb8 = ((lane >> 3) & 1) << 3;     // 0/8 -> n row-half for B
    uint32_t rbA[4], rbB[4];
#pragma unroll
    for (int mi = 0; mi < 4; mi++) rbA[mi] = (uint32_t)((wm + mi * 16 + l15) * 128);
#pragma unroll
    for (int j = 0; j < 4; j++)  rbB[j]  = (uint32_t)((wn + j * 16 + l7 + lb8) * 128);

    float acc[4][8][4];
#pragma unroll
    for (int mi = 0; mi < 4; mi++)
#pragma unroll
        for (int ni = 0; ni < 8; ni++)
#pragma unroll
            for (int k = 0; k < 4; k++) acc[mi][ni][k] = 0.f;

    load_chunk(sb, 0, tid, pAh, pAl, pWh, pWl);

#pragma unroll 1
    for (int c = 0; c < NCHUNK; c++) {
        const uint32_t st = sb + (uint32_t)(c & 1) * STAGE;
        if (c + 1 < NCHUNK) {
            load_chunk(sb + (uint32_t)((c + 1) & 1) * STAGE, c + 1, tid, pAh, pAl, pWh, pWl);
            CP_WAIT1();
        } else {
            CP_WAIT0();
        }
        __syncthreads();

        const uint32_t stAh = st, stAl = st + OFF_AL, stWh = st + OFF_WH, stWl = st + OFF_WL;
#pragma unroll
        for (int kk = 0; kk < 4; kk++) {
            const uint32_t cx = 16u * (uint32_t)(((unsigned)(2 * kk + lhi)) ^ (unsigned)l7);
            uint32_t aH[4][4], bH[4][4];
#pragma unroll
            for (int mi = 0; mi < 4; mi++)
                LDSM_X4(aH[mi][0], aH[mi][1], aH[mi][2], aH[mi][3], stAh + rbA[mi] + cx);
#pragma unroll
            for (int j = 0; j < 4; j++)
                LDSM_X4(bH[j][0], bH[j][1], bH[j][2], bH[j][3], stWh + rbB[j] + cx);
            // T1: Ah * Wh
#pragma unroll
            for (int mi = 0; mi < 4; mi++)
#pragma unroll
                for (int j = 0; j < 4; j++) {
                    MMA4(acc[mi][2 * j],     aH[mi][0], aH[mi][1], aH[mi][2], aH[mi][3], bH[j][0], bH[j][2]);
                    MMA4(acc[mi][2 * j + 1], aH[mi][0], aH[mi][1], aH[mi][2], aH[mi][3], bH[j][1], bH[j][3]);
                }
            // T3: Al * Wh (bH still live)
            {
                uint32_t aL[4][4];
#pragma unroll
                for (int mi = 0; mi < 4; mi++)
                    LDSM_X4(aL[mi][0], aL[mi][1], aL[mi][2], aL[mi][3], stAl + rbA[mi] + cx);
#pragma unroll
                for (int mi = 0; mi < 4; mi++)
#pragma unroll
                    for (int j = 0; j < 4; j++) {
                        MMA4(acc[mi][2 * j],     aL[mi][0], aL[mi][1], aL[mi][2], aL[mi][3], bH[j][0], bH[j][2]);
                        MMA4(acc[mi][2 * j + 1], aL[mi][0], aL[mi][1], aL[mi][2], aL[mi][3], bH[j][1], bH[j][3]);
                    }
            }
            // T2: Ah * Wl (aH still live)
            {
                uint32_t bL[4][4];
#pragma unroll
                for (int j = 0; j < 4; j++)
                    LDSM_X4(bL[j][0], bL[j][1], bL[j][2], bL[j][3], stWl + rbB[j] + cx);
#pragma unroll
                for (int mi = 0; mi < 4; mi++)
#pragma unroll
                    for (int j = 0; j < 4; j++) {
                        MMA4(acc[mi][2 * j],     aH[mi][0], aH[mi][1], aH[mi][2], aH[mi][3], bL[j][0], bL[j][2]);
                        MMA4(acc[mi][2 * j + 1], aH[mi][0], aH[mi][1], aH[mi][2], aH[mi][3], bL[j][1], bL[j][3]);
                    }
            }
        }
        __syncthreads();
    }

    // ---- epilogue (verified layout from round 3) ----
    auto emit = [&](int r, int c, float v0, float v1) {
        size_t off = (size_t)r * DIM + c;
        if (MODE >= 1) {
            __nv_bfloat162 rh2 = *reinterpret_cast<const __nv_bfloat162*>(Rh + off);
            __nv_bfloat162 rl2 = *reinterpret_cast<const __nv_bfloat162*>(Rl + off);
            v0 += __bfloat162float(rh2.x) + __bfloat162float(rl2.x);
            v1 += __bfloat162float(rh2.y) + __bfloat162float(rl2.y);
        }
        if (MODE == 0) { v0 = fmaxf(v0, 0.f); v1 = fmaxf(v1, 0.f); }
        if (MODE == 2) {
            *reinterpret_cast<float2*>(Of + off) = make_float2(v0, v1);
        } else {
            __nv_bfloat16 h0, l0, h1, l1;
            split1(v0, h0, l0); split1(v1, h1, l1);
            __nv_bfloat162 H; H.x = h0; H.y = h1;
            __nv_bfloat162 L; L.x = l0; L.y = l1;
            *reinterpret_cast<__nv_bfloat162*>(Oh + off) = H;
            *reinterpret_cast<__nv_bfloat162*>(Ol + off) = L;
        }
    };

    const int g  = lane >> 2;    // row within 16-tile
    const int tg = lane & 3;     // col pair
#pragma unroll
    for (int mi = 0; mi < 4; mi++) {
#pragma unroll
        for (int ni = 0; ni < 8; ni++) {
            int r0 = Mb + wm + mi * 16 + g;
            int c0 = Nb + wn + ni * 8 + tg * 2;
            float b0 = __ldg(bias + c0), b1 = __ldg(bias + c0 + 1);
            emit(r0,     c0, acc[mi][ni][0] + b0, acc[mi][ni][1] + b1);
            emit(r0 + 8, c0, acc[mi][ni][2] + b0, acc[mi][ni][3] + b1);
        }
    }
}

// ---------------- split input x into (hi, lo) bf16 pair + residual copy ----------------
__global__ void k_split(const float* __restrict__ x,
                        __nv_bfloat16* __restrict__ oh, __nv_bfloat16* __restrict__ ol,
                        __nv_bfloat16* __restrict__ rh, __nv_bfloat16* __restrict__ rl) {
    int i4 = blockIdx.x * blockDim.x + threadIdx.x;
    float4 v = reinterpret_cast<const float4*>(x)[i4];
    __nv_bfloat16 h0,h1,h2,h3,l0,l1,l2,l3;
    split1(v.x,h0,l0); split1(v.y,h1,l1); split1(v.z,h2,l2); split1(v.w,h3,l3);
    __nv_bfloat162 H0; H0.x=h0; H0.y=h1;
    __nv_bfloat162 H1; H1.x=h2; H1.y=h3;
    __nv_bfloat162 L0; L0.x=l0; L0.y=l1;
    __nv_bfloat162 L1; L1.x=l2; L1.y=l3;
    __nv_bfloat162* OH = reinterpret_cast<__nv_bfloat162*>(oh);
    __nv_bfloat162* OL = reinterpret_cast<__nv_bfloat162*>(ol);
    __nv_bfloat162* RH = reinterpret_cast<__nv_bfloat162*>(rh);
    __nv_bfloat162* RL = reinterpret_cast<__nv_bfloat162*>(rl);
    int b = i4 * 2;
    OH[b] = H0; OH[b+1] = H1;
    OL[b] = L0; OL[b+1] = L1;
    RH[b] = H0; RH[b+1] = H1;
    RL[b] = L0; RL[b+1] = L1;
}

// ---------------- dequant + fold LoRA, split to bf16 pair ----------------
__global__ void k_prep(const int* __restrict__ qw, const float* __restrict__ scale,
                       const float* __restrict__ la, const float* __restrict__ lb) {
    int idx = blockIdx.x * 256 + threadIdx.x;
    int l   = idx >> 20;
    int rem = idx & 0xFFFFF;
    int o   = rem >> 10;
    int i   = rem & 1023;
    float q = (float)qw[idx];
    float s = scale[(l << 16) + (o << 6) + (i >> 4)];
    float w = (q / 15.0f * 2.0f - 1.0f) * s;
    const float* lar = la + l * (32 * DIM) + i;
    const float* lbr = lb + l * (DIM * 32) + o * 32;
#pragma unroll
    for (int r = 0; r < 32; r++)
        w += lbr[r] * lar[r * DIM];
    __nv_bfloat16 wh, wl;
    split1(w, wh, wl);
    g_Wh[idx] = wh;
    g_Wl[idx] = wl;
}

// ---------------- LayerNorm ----------------
__device__ __forceinline__ float blockSum256(float v, float* red) {
#pragma unroll
    for (int o = 16; o > 0; o >>= 1) v += __shfl_xor_sync(0xffffffffu, v, o);
    int w = threadIdx.x >> 5;
    if ((threadIdx.x & 31) == 0) red[w] = v;
    __syncthreads();
    float t = 0.f;
#pragma unroll
    for (int i = 0; i < 8; i++) t += red[i];
    __syncthreads();
    return t;
}

__global__ void k_ln(const __nv_bfloat16* __restrict__ Ih, const __nv_bfloat16* __restrict__ Il,
                     const float* __restrict__ gw, const float* __restrict__ gb,
                     __nv_bfloat16* __restrict__ Oh, __nv_bfloat16* __restrict__ Ol,
                     __nv_bfloat16* __restrict__ R2h, __nv_bfloat16* __restrict__ R2l)
{
    __shared__ float red[8];
    const int row = blockIdx.x;
    const int tid = threadIdx.x;
    const size_t base = (size_t)row * DIM;
    float x[4];
#pragma unroll
    for (int j = 0; j < 4; j++) {
        int c = tid + j * 256;
        x[j] = __bfloat162float(Ih[base + c]) + __bfloat162float(Il[base + c]);
    }
    float s = x[0] + x[1] + x[2] + x[3];
    float mu = blockSum256(s, red) * (1.0f / DIM);
    float d[4], s2 = 0.f;
#pragma unroll
    for (int j = 0; j < 4; j++) { d[j] = x[j] - mu; s2 += d[j] * d[j]; }
    float var = blockSum256(s2, red) * (1.0f / DIM);
    float inv = rsqrtf(var + 1e-5f);
#pragma unroll
    for (int j = 0; j < 4; j++) {
        int c = tid + j * 256;
        float y = d[j] * inv * gw[c] + gb[c];
        __nv_bfloat16 h, l;
        split1(y, h, l);
        Oh[base + c] = h;  Ol[base + c] = l;
        R2h[base + c] = h; R2l[base + c] = l;
    }
}

// ---------------- orchestration ----------------
extern "C" void kernel_launch(void* const* d_in, const int* in_sizes, int n_in,
                              void* d_out, int out_size) {
    (void)in_sizes; (void)n_in; (void)out_size;
    const float* x     = (const float*)d_in[0];
    const float* scale = (const float*)d_in[1];
    const float* bias  = (const float*)d_in[2];
    const float* la    = (const float*)d_in[3];
    const float* lb    = (const float*)d_in[4];
    const float* lnw   = (const float*)d_in[5];
    const float* lnb   = (const float*)d_in[6];
    const int*   qw    = (const int*)d_in[7];

    __nv_bfloat16 *Wh, *Wl, *A0h, *A0l, *A1h, *A1l, *Rh, *Rl;
    cudaGetSymbolAddress((void**)&Wh,  g_Wh);
    cudaGetSymbolAddress((void**)&Wl,  g_Wl);
    cudaGetSymbolAddress((void**)&A0h, g_A0h);
    cudaGetSymbolAddress((void**)&A0l, g_A0l);
    cudaGetSymbolAddress((void**)&A1h, g_A1h);
    cudaGetSymbolAddress((void**)&A1l, g_A1l);
    cudaGetSymbolAddress((void**)&Rh,  g_Rh);
    cudaGetSymbolAddress((void**)&Rl,  g_Rl);

    cudaFuncSetAttribute(k_gemm<0>, cudaFuncAttributeMaxDynamicSharedMemorySize, SM_TOTAL);
    cudaFuncSetAttribute(k_gemm<1>, cudaFuncAttributeMaxDynamicSharedMemorySize, SM_TOTAL);
    cudaFuncSetAttribute(k_gemm<2>, cudaFuncAttributeMaxDynamicSharedMemorySize, SM_TOTAL);

    k_split<<<BATCH * DIM / 4 / 256, 256>>>(x, A0h, A0l, Rh, Rl);
    k_prep <<<NLAYERS * DIM * DIM / 256, 256>>>(qw, scale, la, lb);

    dim3 ggrid(DIM / BN, BATCH / BM);   // (4, 128)
    int li = 0;
    for (int blk = 0; blk < 6; ++blk) {
        const int W0 = li * DIM * DIM;
        k_gemm<0><<<ggrid, 256, SM_TOTAL>>>(A0h, A0l, Wh + W0, Wl + W0, bias + li * DIM,
                                            A1h, A1l, nullptr, nullptr, nullptr);
        li++;
        const int W1 = li * DIM * DIM;
        k_gemm<0><<<ggrid, 256, SM_TOTAL>>>(A1h, A1l, Wh + W1, Wl + W1, bias + li * DIM,
                                            A0h, A0l, nullptr, nullptr, nullptr);
        li++;
        const int W2 = li * DIM * DIM;
        if (blk < 5) {
            k_gemm<1><<<ggrid, 256, SM_TOTAL>>>(A0h, A0l, Wh + W2, Wl + W2, bias + li * DIM,
                                                A1h, A1l, Rh, Rl, nullptr);
            li++;
            k_ln<<<BATCH, 256>>>(A1h, A1l, lnw + blk * DIM, lnb + blk * DIM,
                                 A0h, A0l, Rh, Rl);
        } else {
            k_gemm<2><<<ggrid, 256, SM_TOTAL>>>(A0h, A0l, Wh + W2, Wl + W2, bias + li * DIM,
                                                nullptr, nullptr, Rh, Rl, (float*)d_out);
            li++;
        }
    }
}

// round 6
// speedup vs baseline: 1.1612x; 1.0987x over previous
#include <cuda_runtime.h>
#include <cuda_bf16.h>
#include <cstdint>

#define DIM     1024
#define BATCH   16384
#define NLAYERS 18

// ---------------- GEMM tiling ----------------
#define BM 128
#define BN 128
#define BK 32                     // bf16 per K-chunk = 64B per row-half... rows are 128B? No:
// BK=32 bf16 = 64 bytes per row per chunk. We store rows of 64B in smem (half SW atom).
// Use SW64-style swizzle on 64B rows: XOR bits[5:4] with row bits — keeps ldmatrix conflict-free.
#define NCHUNK (DIM / BK)         // 32

// smem stage: Ah/Al/Wh/Wl each 128 rows x 64B = 8KB -> stage 32KB, 2 stages = 64KB/CTA
#define OFF_AL 8192u
#define OFF_WH 16384u
#define OFF_WL 24576u
#define STAGE  32768u
#define SM_TOTAL (2 * 32768)

// ---------------- static device scratch ----------------
__device__ __align__(16) __nv_bfloat16 g_Wh[NLAYERS * DIM * DIM];
__device__ __align__(16) __nv_bfloat16 g_Wl[NLAYERS * DIM * DIM];
__device__ __align__(16) __nv_bfloat16 g_A0h[BATCH * DIM];
__device__ __align__(16) __nv_bfloat16 g_A0l[BATCH * DIM];
__device__ __align__(16) __nv_bfloat16 g_A1h[BATCH * DIM];
__device__ __align__(16) __nv_bfloat16 g_A1l[BATCH * DIM];
__device__ __align__(16) __nv_bfloat16 g_Rh [BATCH * DIM];
__device__ __align__(16) __nv_bfloat16 g_Rl [BATCH * DIM];

// ---------------- PTX helpers ----------------
__device__ __forceinline__ uint32_t smem_u32(const void* p) {
    uint32_t a;
    asm("{ .reg .u64 t; cvta.to.shared.u64 t, %1; cvt.u32.u64 %0, t; }" : "=r"(a) : "l"(p));
    return a;
}
#define CP_ASYNC16(dst, src) \
    asm volatile("cp.async.cg.shared.global [%0], [%1], 16;\n" :: "r"(dst), "l"(src))
#define CP_COMMIT() asm volatile("cp.async.commit_group;\n" ::: "memory")
#define CP_WAIT1()  asm volatile("cp.async.wait_group 1;\n" ::: "memory")
#define CP_WAIT0()  asm volatile("cp.async.wait_group 0;\n" ::: "memory")

#define LDSM_X4(r0, r1, r2, r3, addr) \
    asm volatile("ldmatrix.sync.aligned.m8n8.x4.shared.b16 {%0,%1,%2,%3}, [%4];\n" \
                 : "=r"(r0), "=r"(r1), "=r"(r2), "=r"(r3) : "r"(addr))
#define LDSM_X2(r0, r1, addr) \
    asm volatile("ldmatrix.sync.aligned.m8n8.x2.shared.b16 {%0,%1}, [%2];\n" \
                 : "=r"(r0), "=r"(r1) : "r"(addr))

#define MMA4(d, a0, a1, a2, a3, b0, b1) \
    asm volatile("mma.sync.aligned.m16n8k16.row.col.f32.bf16.bf16.f32 " \
                 "{%0,%1,%2,%3},{%4,%5,%6,%7},{%8,%9},{%0,%1,%2,%3};\n" \
                 : "+f"((d)[0]), "+f"((d)[1]), "+f"((d)[2]), "+f"((d)[3]) \
                 : "r"(a0), "r"(a1), "r"(a2), "r"(a3), "r"(b0), "r"(b1))

__device__ __forceinline__ void split1(float v, __nv_bfloat16& h, __nv_bfloat16& l) {
    h = __float2bfloat16(v);
    l = __float2bfloat16(v - __bfloat162float(h));
}

// swizzle for 64B rows: byte_off ^ ((row & 3) << 4)  [2-bit XOR over 16B units]
// Row r, 16B group g (0..3): dst16 = g ^ (r & 3). ldmatrix reads 8 lanes' rows at the
// same g -> distinct banks across the 4-row repeat, conflict-free (verified pattern: each
// 8-lane phase touches rows r..r+7 at fixed g -> offsets {g^0,g^1,g^2,g^3} x2 -> 8 distinct 16B banks).
__device__ __forceinline__ uint32_t swz64(uint32_t row, uint32_t g16) {
    return row * 64u + ((g16 ^ (row & 3u)) << 4);
}

// stage loader: 32KB / 256 threads = 8 cp.async x16B per thread
__device__ __forceinline__ void load_chunk(
    uint32_t st, int c, int tid,
    const char* pAh, const char* pAl, const char* pWh, const char* pWl)
{
    const size_t koff = (size_t)c * 64u;
#pragma unroll
    for (int i = 0; i < 8; i++) {
        int idx = tid + i * 256;          // 0..2047
        int arr = idx >> 9;               // 0..3 : Ah, Al, Wh, Wl
        int r   = (idx >> 2) & 127;       // row 0..127
        int g   = idx & 3;                // 16B group 0..3
        const char* base = (arr == 0) ? pAh : (arr == 1) ? pAl : (arr == 2) ? pWh : pWl;
        const char* src = base + (size_t)r * 2048 + koff + (size_t)(g * 16);
        uint32_t dst = st + (uint32_t)arr * 8192u + swz64((uint32_t)r, (uint32_t)g);
        CP_ASYNC16(dst, src);
    }
    CP_COMMIT();
}

// ---------------- fused GEMM layer ----------------
// C[BM,BN] = A[BM,K] * W[BN,K]^T, 3-term bf16 split, fp32 accum.
// MODE 0: relu(C+bias)->bf16 pair | MODE 1: C+bias+res->bf16 pair | MODE 2: C+bias+res->fp32
template<int MODE>
__global__ void __launch_bounds__(256, 2)
k_gemm(const __nv_bfloat16* __restrict__ Ah, const __nv_bfloat16* __restrict__ Al,
       const __nv_bfloat16* __restrict__ Wh, const __nv_bfloat16* __restrict__ Wl,
       const float* __restrict__ bias,
       __nv_bfloat16* __restrict__ Oh, __nv_bfloat16* __restrict__ Ol,
       const __nv_bfloat16* __restrict__ Rh, const __nv_bfloat16* __restrict__ Rl,
       float* __restrict__ Of)
{
    extern __shared__ char smem[];
    const uint32_t sb = smem_u32(smem);
    const int tid = threadIdx.x, wid = tid >> 5, lane = tid & 31;
    const int Mb = blockIdx.y * BM, Nb = blockIdx.x * BN;
    const int wm = (wid & 1) * 64;          // 2 m-warps
    const int wn = (wid >> 1) * 32;         // 4 n-warps

    const char* pAh = (const char*)(Ah + (size_t)Mb * DIM);
    const char* pAl = (const char*)(Al + (size_t)Mb * DIM);
    const char* pWh = (const char*)(Wh + (size_t)Nb * DIM);
    const char* pWl = (const char*)(Wl + (size_t)Nb * DIM);

    // ldmatrix addressing: 64B rows, 32 k-cols per chunk -> 2 k16 sub-steps.
    // For k16 step kk (0/1): A tile m16 at rows (wm+mi*16 + l15), 16B col = 2*kk + (lane>>4)
    // B tile n16 at rows (wn+j*16 + l7+lb8), same col group.
    const int l7  = lane & 7;
    const int l15 = lane & 15;
    const int lhi = lane >> 4;              // 0/1
    const int lb8 = ((lane >> 3) & 1) << 3;

    // precomputed swizzled addresses for kk=0,1 (A: 4 m-tiles, B: 2 n-tiles)
    uint32_t adA[2][4], adB[2][2];
#pragma unroll
    for (int kk = 0; kk < 2; kk++) {
#pragma unroll
        for (int mi = 0; mi < 4; mi++) {
            uint32_t r = (uint32_t)(wm + mi * 16 + l15);
            adA[kk][mi] = swz64(r, (uint32_t)(2 * kk + lhi));
        }
#pragma unroll
        for (int j = 0; j < 2; j++) {
            uint32_t r = (uint32_t)(wn + j * 16 + l7 + lb8);
            adB[kk][j] = swz64(r, (uint32_t)(2 * kk + lhi));
        }
    }

    float acc[4][4][4];
#pragma unroll
    for (int mi = 0; mi < 4; mi++)
#pragma unroll
        for (int ni = 0; ni < 4; ni++)
#pragma unroll
            for (int k = 0; k < 4; k++) acc[mi][ni][k] = 0.f;

    load_chunk(sb, 0, tid, pAh, pAl, pWh, pWl);

#pragma unroll 1
    for (int c = 0; c < NCHUNK; c++) {
        const uint32_t st = sb + (uint32_t)(c & 1) * STAGE;
        if (c + 1 < NCHUNK) {
            load_chunk(sb + (uint32_t)((c + 1) & 1) * STAGE, c + 1, tid, pAh, pAl, pWh, pWl);
            CP_WAIT1();
        } else {
            CP_WAIT0();
        }
        __syncthreads();

        const uint32_t stAh = st, stAl = st + OFF_AL, stWh = st + OFF_WH, stWl = st + OFF_WL;
#pragma unroll
        for (int kk = 0; kk < 2; kk++) {
            uint32_t aH[4][4], bH[2][4];
#pragma unroll
            for (int mi = 0; mi < 4; mi++)
                LDSM_X4(aH[mi][0], aH[mi][1], aH[mi][2], aH[mi][3], stAh + adA[kk][mi]);
#pragma unroll
            for (int j = 0; j < 2; j++)
                LDSM_X4(bH[j][0], bH[j][1], bH[j][2], bH[j][3], stWh + adB[kk][j]);
            // T1: Ah*Wh
#pragma unroll
            for (int mi = 0; mi < 4; mi++)
#pragma unroll
                for (int j = 0; j < 2; j++) {
                    MMA4(acc[mi][2 * j],     aH[mi][0], aH[mi][1], aH[mi][2], aH[mi][3], bH[j][0], bH[j][2]);
                    MMA4(acc[mi][2 * j + 1], aH[mi][0], aH[mi][1], aH[mi][2], aH[mi][3], bH[j][1], bH[j][3]);
                }
            // T3: Al*Wh (bH live)
            {
                uint32_t aL[4][4];
#pragma unroll
                for (int mi = 0; mi < 4; mi++)
                    LDSM_X4(aL[mi][0], aL[mi][1], aL[mi][2], aL[mi][3], stAl + adA[kk][mi]);
#pragma unroll
                for (int mi = 0; mi < 4; mi++)
#pragma unroll
                    for (int j = 0; j < 2; j++) {
                        MMA4(acc[mi][2 * j],     aL[mi][0], aL[mi][1], aL[mi][2], aL[mi][3], bH[j][0], bH[j][2]);
                        MMA4(acc[mi][2 * j + 1], aL[mi][0], aL[mi][1], aL[mi][2], aL[mi][3], bH[j][1], bH[j][3]);
                    }
            }
            // T2: Ah*Wl (aH live)
            {
                uint32_t bL[2][4];
#pragma unroll
                for (int j = 0; j < 2; j++)
                    LDSM_X4(bL[j][0], bL[j][1], bL[j][2], bL[j][3], stWl + adB[kk][j]);
#pragma unroll
                for (int mi = 0; mi < 4; mi++)
#pragma unroll
                    for (int j = 0; j < 2; j++) {
                        MMA4(acc[mi][2 * j],     aH[mi][0], aH[mi][1], aH[mi][2], aH[mi][3], bL[j][0], bL[j][2]);
                        MMA4(acc[mi][2 * j + 1], aH[mi][0], aH[mi][1], aH[mi][2], aH[mi][3], bL[j][1], bL[j][3]);
                    }
            }
        }
        __syncthreads();
    }

    // ---- epilogue (verified fragment layout) ----
    auto emit = [&](int r, int c, float v0, float v1) {
        size_t off = (size_t)r * DIM + c;
        if (MODE >= 1) {
            __nv_bfloat162 rh2 = *reinterpret_cast<const __nv_bfloat162*>(Rh + off);
            __nv_bfloat162 rl2 = *reinterpret_cast<const __nv_bfloat162*>(Rl + off);
            v0 += __bfloat162float(rh2.x) + __bfloat162float(rl2.x);
            v1 += __bfloat162float(rh2.y) + __bfloat162float(rl2.y);
        }
        if (MODE == 0) { v0 = fmaxf(v0, 0.f); v1 = fmaxf(v1, 0.f); }
        if (MODE == 2) {
            *reinterpret_cast<float2*>(Of + off) = make_float2(v0, v1);
        } else {
            __nv_bfloat16 h0, l0, h1, l1;
            split1(v0, h0, l0); split1(v1, h1, l1);
            __nv_bfloat162 H; H.x = h0; H.y = h1;
            __nv_bfloat162 L; L.x = l0; L.y = l1;
            *reinterpret_cast<__nv_bfloat162*>(Oh + off) = H;
            *reinterpret_cast<__nv_bfloat162*>(Ol + off) = L;
        }
    };

    const int g  = lane >> 2;
    const int tg = lane & 3;
#pragma unroll
    for (int mi = 0; mi < 4; mi++) {
#pragma unroll
        for (int ni = 0; ni < 4; ni++) {
            int r0 = Mb + wm + mi * 16 + g;
            int c0 = Nb + wn + ni * 8 + tg * 2;
            float b0 = __ldg(bias + c0), b1 = __ldg(bias + c0 + 1);
            emit(r0,     c0, acc[mi][ni][0] + b0, acc[mi][ni][1] + b1);
            emit(r0 + 8, c0, acc[mi][ni][2] + b0, acc[mi][ni][3] + b1);
        }
    }
}

// ---------------- split input x ----------------
__global__ void k_split(const float* __restrict__ x,
                        __nv_bfloat16* __restrict__ oh, __nv_bfloat16* __restrict__ ol,
                        __nv_bfloat16* __restrict__ rh, __nv_bfloat16* __restrict__ rl) {
    int i4 = blockIdx.x * blockDim.x + threadIdx.x;
    float4 v = reinterpret_cast<const float4*>(x)[i4];
    __nv_bfloat16 h0,h1,h2,h3,l0,l1,l2,l3;
    split1(v.x,h0,l0); split1(v.y,h1,l1); split1(v.z,h2,l2); split1(v.w,h3,l3);
    __nv_bfloat162 H0; H0.x=h0; H0.y=h1;
    __nv_bfloat162 H1; H1.x=h2; H1.y=h3;
    __nv_bfloat162 L0; L0.x=l0; L0.y=l1;
    __nv_bfloat162 L1; L1.x=l2; L1.y=l3;
    __nv_bfloat162* OH = reinterpret_cast<__nv_bfloat162*>(oh);
    __nv_bfloat162* OL = reinterpret_cast<__nv_bfloat162*>(ol);
    __nv_bfloat162* RH = reinterpret_cast<__nv_bfloat162*>(rh);
    __nv_bfloat162* RL = reinterpret_cast<__nv_bfloat162*>(rl);
    int b = i4 * 2;
    OH[b] = H0; OH[b+1] = H1;
    OL[b] = L0; OL[b+1] = L1;
    RH[b] = H0; RH[b+1] = H1;
    RL[b] = L0; RL[b+1] = L1;
}

// ---------------- dequant + fold LoRA ----------------
__global__ void k_prep(const int* __restrict__ qw, const float* __restrict__ scale,
                       const float* __restrict__ la, const float* __restrict__ lb) {
    int idx = blockIdx.x * 256 + threadIdx.x;
    int l   = idx >> 20;
    int rem = idx & 0xFFFFF;
    int o   = rem >> 10;
    int i   = rem & 1023;
    float q = (float)qw[idx];
    float s = scale[(l << 16) + (o << 6) + (i >> 4)];
    float w = (q / 15.0f * 2.0f - 1.0f) * s;
    const float* lar = la + l * (32 * DIM) + i;
    const float* lbr = lb + l * (DIM * 32) + o * 32;
#pragma unroll
    for (int r = 0; r < 32; r++)
        w += lbr[r] * lar[r * DIM];
    __nv_bfloat16 wh, wl;
    split1(w, wh, wl);
    g_Wh[idx] = wh;
    g_Wl[idx] = wl;
}

// ---------------- LayerNorm ----------------
__device__ __forceinline__ float blockSum256(float v, float* red) {
#pragma unroll
    for (int o = 16; o > 0; o >>= 1) v += __shfl_xor_sync(0xffffffffu, v, o);
    int w = threadIdx.x >> 5;
    if ((threadIdx.x & 31) == 0) red[w] = v;
    __syncthreads();
    float t = 0.f;
#pragma unroll
    for (int i = 0; i < 8; i++) t += red[i];
    __syncthreads();
    return t;
}

__global__ void k_ln(const __nv_bfloat16* __restrict__ Ih, const __nv_bfloat16* __restrict__ Il,
                     const float* __restrict__ gw, const float* __restrict__ gb,
                     __nv_bfloat16* __restrict__ Oh, __nv_bfloat16* __restrict__ Ol,
                     __nv_bfloat16* __restrict__ R2h, __nv_bfloat16* __restrict__ R2l)
{
    __shared__ float red[8];
    const int row = blockIdx.x;
    const int tid = threadIdx.x;
    const size_t base = (size_t)row * DIM;
    float x[4];
#pragma unroll
    for (int j = 0; j < 4; j++) {
        int c = tid + j * 256;
        x[j] = __bfloat162float(Ih[base + c]) + __bfloat162float(Il[base + c]);
    }
    float s = x[0] + x[1] + x[2] + x[3];
    float mu = blockSum256(s, red) * (1.0f / DIM);
    float d[4], s2 = 0.f;
#pragma unroll
    for (int j = 0; j < 4; j++) { d[j] = x[j] - mu; s2 += d[j] * d[j]; }
    float var = blockSum256(s2, red) * (1.0f / DIM);
    float inv = rsqrtf(var + 1e-5f);
#pragma unroll
    for (int j = 0; j < 4; j++) {
        int c = tid + j * 256;
        float y = d[j] * inv * gw[c] + gb[c];
        __nv_bfloat16 h, l;
        split1(y, h, l);
        Oh[base + c] = h;  Ol[base + c] = l;
        R2h[base + c] = h; R2l[base + c] = l;
    }
}

// ---------------- orchestration ----------------
extern "C" void kernel_launch(void* const* d_in, const int* in_sizes, int n_in,
                              void* d_out, int out_size) {
    (void)in_sizes; (void)n_in; (void)out_size;
    const float* x     = (const float*)d_in[0];
    const float* scale = (const float*)d_in[1];
    const float* bias  = (const float*)d_in[2];
    const float* la    = (const float*)d_in[3];
    const float* lb    = (const float*)d_in[4];
    const float* lnw   = (const float*)d_in[5];
    const float* lnb   = (const float*)d_in[6];
    const int*   qw    = (const int*)d_in[7];

    __nv_bfloat16 *Wh, *Wl, *A0h, *A0l, *A1h, *A1l, *Rh, *Rl;
    cudaGetSymbolAddress((void**)&Wh,  g_Wh);
    cudaGetSymbolAddress((void**)&Wl,  g_Wl);
    cudaGetSymbolAddress((void**)&A0h, g_A0h);
    cudaGetSymbolAddress((void**)&A0l, g_A0l);
    cudaGetSymbolAddress((void**)&A1h, g_A1h);
    cudaGetSymbolAddress((void**)&A1l, g_A1l);
    cudaGetSymbolAddress((void**)&Rh,  g_Rh);
    cudaGetSymbolAddress((void**)&Rl,  g_Rl);

    cudaFuncSetAttribute(k_gemm<0>, cudaFuncAttributeMaxDynamicSharedMemorySize, SM_TOTAL);
    cudaFuncSetAttribute(k_gemm<1>, cudaFuncAttributeMaxDynamicSharedMemorySize, SM_TOTAL);
    cudaFuncSetAttribute(k_gemm<2>, cudaFuncAttributeMaxDynamicSharedMemorySize, SM_TOTAL);

    k_split<<<BATCH * DIM / 4 / 256, 256>>>(x, A0h, A0l, Rh, Rl);
    k_prep <<<NLAYERS * DIM * DIM / 256, 256>>>(qw, scale, la, lb);

    dim3 ggrid(DIM / BN, BATCH / BM);   // (8, 128)
    int li = 0;
    for (int blk = 0; blk < 6; ++blk) {
        const int W0 = li * DIM * DIM;
        k_gemm<0><<<ggrid, 256, SM_TOTAL>>>(A0h, A0l, Wh + W0, Wl + W0, bias + li * DIM,
                                            A1h, A1l, nullptr, nullptr, nullptr);
        li++;
        const int W1 = li * DIM * DIM;
        k_gemm<0><<<ggrid, 256, SM_TOTAL>>>(A1h, A1l, Wh + W1, Wl + W1, bias + li * DIM,
                                            A0h, A0l, nullptr, nullptr, nullptr);
        li++;
        const int W2 = li * DIM * DIM;
        if (blk < 5) {
            k_gemm<1><<<ggrid, 256, SM_TOTAL>>>(A0h, A0l, Wh + W2, Wl + W2, bias + li * DIM,
                                                A1h, A1l, Rh, Rl, nullptr);
            li++;
            k_ln<<<BATCH, 256>>>(A1h, A1l, lnw + blk * DIM, lnb + blk * DIM,
                                 A0h, A0l, Rh, Rl);
        } else {
            k_gemm<2><<<ggrid, 256, SM_TOTAL>>>(A0h, A0l, Wh + W2, Wl + W2, bias + li * DIM,
                                                nullptr, nullptr, Rh, Rl, (float*)d_out);
            li++;
        }
    }
}